// round 8
// baseline (speedup 1.0000x reference)
#include <cuda_runtime.h>
#include <cuda_bf16.h>

#define C_CLASSES 1000
#define NV4 250            // 1000 floats = 250 float4
#define SMOOTH 0.1f
#define GRID 592           // 148 SMs * 4 blocks — all co-resident (GB300 has 152 SMs)
#define NWARPS (GRID * 8)  // 4736 warps

// device scratch (no allocations allowed)
__device__ __nv_bfloat16 g_Ab[C_CLASSES * C_CLASSES];  // pre-scaled beta_t*A[t][j], bf16
__device__ float g_beta[C_CLASSES];
__device__ float g_rowS[C_CLASSES];
__device__ float g_blocksum[GRID];
__device__ unsigned g_c1, g_c2;    // barrier counters (reset to 0 at kernel end)

__device__ __forceinline__ float warpMax(float v) {
    #pragma unroll
    for (int o = 16; o; o >>= 1) v = fmaxf(v, __shfl_xor_sync(0xffffffffu, v, o));
    return v;
}
__device__ __forceinline__ float warpSum(float v) {
    #pragma unroll
    for (int o = 16; o; o >>= 1) v += __shfl_xor_sync(0xffffffffu, v, o);
    return v;
}

__global__ __launch_bounds__(256, 4)
void fused_kernel(const float* __restrict__ x,
                  const float* __restrict__ class_avg,
                  const int* __restrict__ target,
                  float* __restrict__ out, float invB, int B) {
    const int tid  = threadIdx.x;
    const int wid  = tid >> 5;
    const int lane = tid & 31;
    const int gw   = blockIdx.x * 8 + wid;      // global warp id 0..4735
    const bool v7  = (lane < NV4 - 224);        // lane < 26

    // ===================== Phase A: softmax prep (warp-per-row) =====================
    if (gw < C_CLASSES) {
        const int t = gw;
        const float4* row = (const float4*)(class_avg + (size_t)t * C_CLASSES);
        float4 v[8];
        #pragma unroll
        for (int k = 0; k < 7; k++) v[k] = __ldg(row + lane + k * 32);
        v[7] = v7 ? __ldg(row + lane + 224)
                  : make_float4(-3.402823e38f, -3.402823e38f, -3.402823e38f, -3.402823e38f);

        float m = -3.402823e38f;
        #pragma unroll
        for (int k = 0; k < 8; k++)
            m = fmaxf(m, fmaxf(fmaxf(v[k].x, v[k].y), fmaxf(v[k].z, v[k].w)));
        const float M = warpMax(m);

        const int tq = t >> 2, tc = t & 3;
        float s = 0.f, diag = 0.f;
        #pragma unroll
        for (int k = 0; k < 8; k++) {
            v[k].x = __expf(v[k].x - M); v[k].y = __expf(v[k].y - M);
            v[k].z = __expf(v[k].z - M); v[k].w = __expf(v[k].w - M);
            s += (v[k].x + v[k].y) + (v[k].z + v[k].w);
            if (lane + k * 32 == tq)
                diag = (tc == 0) ? v[k].x : (tc == 1) ? v[k].y : (tc == 2) ? v[k].z : v[k].w;
        }
        const float S = warpSum(s);
        diag = warpSum(diag);

        const float Att  = diag / S;
        const float offm = 1.0f - Att;
        const float beta = SMOOTH / offm;
        if (lane == 0) {
            g_beta[t] = beta;
            g_rowS[t] = (1.0f - SMOOTH) + SMOOTH * ((float)(C_CLASSES - 2) + Att) / offm;
        }
        const float sc = beta / S;

        uint2* ab = (uint2*)(g_Ab + (size_t)t * C_CLASSES);
        #pragma unroll
        for (int k = 0; k < 7; k++) {
            __nv_bfloat162 lo = __float22bfloat162_rn(make_float2(v[k].x * sc, v[k].y * sc));
            __nv_bfloat162 hi = __float22bfloat162_rn(make_float2(v[k].z * sc, v[k].w * sc));
            uint2 o; o.x = *(unsigned*)&lo; o.y = *(unsigned*)&hi;
            ab[lane + k * 32] = o;
        }
        if (v7) {
            __nv_bfloat162 lo = __float22bfloat162_rn(make_float2(v[7].x * sc, v[7].y * sc));
            __nv_bfloat162 hi = __float22bfloat162_rn(make_float2(v[7].z * sc, v[7].w * sc));
            uint2 o; o.x = *(unsigned*)&lo; o.y = *(unsigned*)&hi;
            ab[lane + 224] = o;
        }
    }

    // ===================== Grid barrier #1 =====================
    if (tid == 0) {
        __threadfence();
        atomicAdd(&g_c1, 1u);
        while (*(volatile unsigned*)&g_c1 < (unsigned)GRID) __nanosleep(64);
    }
    __syncthreads();
    __threadfence();

    // ===================== Phase B: loss (warp-per-row, grid-strided) =====================
    float acc = 0.f;   // identical across lanes after warpSums
    for (int i = gw; i < B; i += NWARPS) {
        const int t = __ldg(target + i);
        const float4* xr = (const float4*)(x + (size_t)i * C_CLASSES);
        const uint2*  ar = (const uint2*)(g_Ab + (size_t)t * C_CLASSES);

        float4 xv[8]; uint2 av[8];
        #pragma unroll
        for (int k = 0; k < 7; k++) xv[k] = __ldcs(xr + lane + k * 32);
        xv[7] = v7 ? __ldcs(xr + lane + 224) : make_float4(0.f, 0.f, 0.f, 0.f);
        #pragma unroll
        for (int k = 0; k < 7; k++) av[k] = __ldg(ar + lane + k * 32);
        av[7] = v7 ? __ldg(ar + lane + 224) : make_uint2(0u, 0u);

        float m = -3.402823e38f;
        #pragma unroll
        for (int k = 0; k < 7; k++)
            m = fmaxf(m, fmaxf(fmaxf(xv[k].x, xv[k].y), fmaxf(xv[k].z, xv[k].w)));
        if (v7) m = fmaxf(m, fmaxf(fmaxf(xv[7].x, xv[7].y), fmaxf(xv[7].z, xv[7].w)));
        const float M = warpMax(m);

        const int tq = t >> 2, tc = t & 3;
        float es = 0.f, sx = 0.f, dt = 0.f, xt = 0.f;
        #pragma unroll
        for (int k = 0; k < 8; k++) {
            if (k == 7 && !v7) break;
            es += (__expf(xv[k].x - M) + __expf(xv[k].y - M)) +
                  (__expf(xv[k].z - M) + __expf(xv[k].w - M));
            sx += (xv[k].x + xv[k].y) + (xv[k].z + xv[k].w);
            const float2 a01 = __bfloat1622float2(*(const __nv_bfloat162*)&av[k].x);
            const float2 a23 = __bfloat1622float2(*(const __nv_bfloat162*)&av[k].y);
            dt = fmaf(xv[k].x, a01.x, fmaf(xv[k].y, a01.y,
                 fmaf(xv[k].z, a23.x, fmaf(xv[k].w, a23.y, dt))));
            if (lane + k * 32 == tq)
                xt = (tc == 0) ? xv[k].x : (tc == 1) ? xv[k].y : (tc == 2) ? xv[k].z : xv[k].w;
        }
        es = warpSum(es); sx = warpSum(sx); dt = warpSum(dt); xt = warpSum(xt);

        const float lse = M + __logf(es);
        acc += lse * __ldg(&g_rowS[t]) - __ldg(&g_beta[t]) * sx + dt - 0.8f * xt;
    }

    // per-block partial (fixed-order, deterministic)
    __shared__ float spart[8];
    if (lane == 0) spart[wid] = acc;
    __syncthreads();
    if (tid == 0) {
        float bs = 0.f;
        #pragma unroll
        for (int k = 0; k < 8; k++) bs += spart[k];
        g_blocksum[blockIdx.x] = bs;
        __threadfence();
        atomicAdd(&g_c2, 1u);
    }

    // ===================== Phase C: block 0 final reduce =====================
    if (blockIdx.x == 0) {
        if (tid == 0) {
            while (*(volatile unsigned*)&g_c2 < (unsigned)GRID) __nanosleep(64);
        }
        __syncthreads();
        __threadfence();

        const volatile float* bsum = (const volatile float*)g_blocksum;
        float s = 0.f;
        for (int k = tid; k < GRID; k += 256) s += bsum[k];
        s = warpSum(s);
        __shared__ float sm[8];
        if (lane == 0) sm[tid >> 5] = s;
        __syncthreads();
        if (tid == 0) {
            float tot = 0.f;
            #pragma unroll
            for (int k = 0; k < 8; k++) tot += sm[k];
            out[0] = tot * invB;
            __threadfence();
            g_c1 = 0u;          // reset for next graph replay (all adds already landed)
            g_c2 = 0u;
        }
    }
}

extern "C" void kernel_launch(void* const* d_in, const int* in_sizes, int n_in,
                              void* d_out, int out_size) {
    const float* x   = (const float*)d_in[0];
    const float* ca  = (const float*)d_in[1];
    const int*   tgt = (const int*)d_in[2];   // jnp.int64 w/o x64 => int32 on device
    float* out = (float*)d_out;

    const int B = in_sizes[2];                // 65536
    fused_kernel<<<GRID, 256>>>(x, ca, tgt, out, 1.0f / (float)B, B);
}